// round 11
// baseline (speedup 1.0000x reference)
#include <cuda_runtime.h>
#include <stdint.h>

#define T_DIM 8
#define C_DIM 4
#define H_DIM 1024
#define W_DIM 1024
#define NIMG  (T_DIM * C_DIM)
#define NGRID 16
#define NCELLS (NGRID * NGRID)
#define THRESH 0.65f
#define NUM_FG 40
#define NUM_BG 1
#define MAX_PTS 42
#define ROW_F4 (W_DIM / 4)   // 256
#define BLOCKS_PER_IMG 32    // 1024 blocks total: block = half cell-row, 4 warps, 2 cells/warp

// Scratch (__device__ globals). Each cell has exactly ONE writer warp, and the
// written value is a pure function of the inputs -> plain stores are idempotent
// across graph replays (no init kernel, no atomics needed).
__device__ unsigned long long g_cmax[NIMG * NCELLS]; // (score_bits<<32) | ~flat_idx  (max, min-idx tie-break)
__device__ unsigned long long g_cmin[NIMG * NCELLS]; // (score_bits<<32) |  flat_idx  (min, min-idx tie-break)
__device__ unsigned int       g_cnt[NIMG];           // arrival counters; last block resets to 0

static __device__ __forceinline__ unsigned long long umaxll(unsigned long long a, unsigned long long b){ return a > b ? a : b; }
static __device__ __forceinline__ unsigned long long uminll(unsigned long long a, unsigned long long b){ return a < b ? a : b; }

__global__ void __launch_bounds__(128)
fused_kernel(const float* __restrict__ sim,
             const int*   __restrict__ ori,
             float*       __restrict__ out,
             int write_nums)
{
    const int blk  = blockIdx.x;             // 0..1023
    const int img  = blk >> 5;               // 32 images
    const int sub  = blk & 31;
    const int cy   = sub >> 1;               // cell row 0..15
    const int half = sub & 1;                // left/right half of the row
    const int tid  = threadIdx.x;            // 0..127
    const int w    = tid >> 5;               // warp 0..3: owns cells cx = half*8 + 2w + {0,1}
    const int lane = tid & 31;
    const float4* base = (const float4*)(sim + (size_t)img * (H_DIM * W_DIM));

    // Lane geometry inside a chunk (8 rows x 64 cols of one cell):
    //   it in 0..3 covers row pair (it*2 + rsub); lanes 0-15 / 16-31 each cover
    //   a full 256B row -> every LDG.128 is perfectly coalesced.
    const int rsub = lane >> 4;              // 0..1
    const int csub = lane & 15;              // 0..15

    // q = 0..15 linear chunk id: cell = half*8 + 2w + (q>>3), chunk c = q&7.
    #define A0(q) ((cy * 64 + ((q) & 7) * 8 + rsub) * ROW_F4 + (half * 8 + 2 * w + ((q) >> 3)) * 16 + csub)

    // Depth-2 software pipeline: 3-buffer ring, loads issued 2 chunks ahead.
    float4 buf[3][4];
    {
        const int a0 = A0(0), a1 = A0(1);
        #pragma unroll
        for (int it = 0; it < 4; it++) buf[0][it] = __ldg(base + a0 + it * (2 * ROW_F4));
        #pragma unroll
        for (int it = 0; it < 4; it++) buf[1][it] = __ldg(base + a1 + it * (2 * ROW_F4));
    }

    const float INF = __uint_as_float(0x7f800000u);
    float vmax0 = 0.0f, vmin0 = INF;         // scores in [0,1): safe bounds, bit-monotone
    float vmax1 = 0.0f, vmin1 = INF;
    int bqmax0 = 0, bqmin0 = 0, bqmax1 = 8, bqmin1 = 8;

    // Single continuous 16-chunk loop: the load stream never pauses mid-warp.
    #pragma unroll
    for (int q = 0; q < 16; q++) {
        if (q < 14) {                        // prefetch 2 ahead (crosses the cell boundary)
            const int a = A0(q + 2);
            #pragma unroll
            for (int it = 0; it < 4; it++)
                buf[(q + 2) % 3][it] = __ldg(base + a + it * (2 * ROW_F4));
        }
        const float4* cur = buf[q % 3];
        float mx0 = fmaxf(fmaxf(cur[0].x, cur[0].y), fmaxf(cur[0].z, cur[0].w));
        float mx1 = fmaxf(fmaxf(cur[1].x, cur[1].y), fmaxf(cur[1].z, cur[1].w));
        float mx2 = fmaxf(fmaxf(cur[2].x, cur[2].y), fmaxf(cur[2].z, cur[2].w));
        float mx3 = fmaxf(fmaxf(cur[3].x, cur[3].y), fmaxf(cur[3].z, cur[3].w));
        float cmax = fmaxf(fmaxf(mx0, mx1), fmaxf(mx2, mx3));
        float mn0 = fminf(fminf(cur[0].x, cur[0].y), fminf(cur[0].z, cur[0].w));
        float mn1 = fminf(fminf(cur[1].x, cur[1].y), fminf(cur[1].z, cur[1].w));
        float mn2 = fminf(fminf(cur[2].x, cur[2].y), fminf(cur[2].z, cur[2].w));
        float mn3 = fminf(fminf(cur[3].x, cur[3].y), fminf(cur[3].z, cur[3].w));
        float cmin = fminf(fminf(mn0, mn1), fminf(mn2, mn3));
        // Chunk-granular deferred tracking; strict compare keeps the FIRST
        // chunk achieving the extremum (chunks ascend in flat index).
        if (q < 8) {                         // compile-time split (loop fully unrolled)
            if (cmax > vmax0) { vmax0 = cmax; bqmax0 = q; }
            if (cmin < vmin0) { vmin0 = cmin; bqmin0 = q; }
        } else {
            if (cmax > vmax1) { vmax1 = cmax; bqmax1 = q; }
            if (cmin < vmin1) { vmin1 = cmin; bqmin1 = q; }
        }
    }

    // ---- merged tail: both cells at once ----
    // Warp value reductions via single-instruction REDUX (scores positive ->
    // unsigned bit order == float order).
    float wmax0 = __uint_as_float(__reduce_max_sync(0xffffffffu, __float_as_uint(vmax0)));
    float wmin0 = __uint_as_float(__reduce_min_sync(0xffffffffu, __float_as_uint(vmin0)));
    float wmax1 = __uint_as_float(__reduce_max_sync(0xffffffffu, __float_as_uint(vmax1)));
    float wmin1 = __uint_as_float(__reduce_min_sync(0xffffffffu, __float_as_uint(vmin1)));

    // Deferred index resolution: matching lanes re-load their best chunk
    // (64B each, L2-resident) and scan 16 values DESCENDING so overwrite
    // keeps the smallest flat index (reference first-occurrence semantics).
    #define RESOLVE(cand, hit, bq, wval)                                              \
        unsigned cand = 0xffffffffu;                                                  \
        if (hit) {                                                                    \
            const int q = bq;                                                         \
            const int a = A0(q);                                                      \
            const int row0 = cy * 64 + (q & 7) * 8 + rsub;                            \
            const int col  = ((half * 8 + 2 * w + (q >> 3)) * 16 + csub) * 4;         \
            _Pragma("unroll")                                                         \
            for (int it = 3; it >= 0; it--) {                                         \
                float4 v = __ldg(base + a + it * (2 * ROW_F4));                       \
                unsigned i0 = (unsigned)((row0 + it * 2) * W_DIM + col);              \
                if (v.w == wval) cand = i0 + 3;                                       \
                if (v.z == wval) cand = i0 + 2;                                       \
                if (v.y == wval) cand = i0 + 1;                                       \
                if (v.x == wval) cand = i0;                                           \
            }                                                                         \
        }

    RESOLVE(candMax0, vmax0 == wmax0, bqmax0, wmax0)
    RESOLVE(candMin0, vmin0 == wmin0, bqmin0, wmin0)
    RESOLVE(candMax1, vmax1 == wmax1, bqmax1, wmax1)
    RESOLVE(candMin1, vmin1 == wmin1, bqmin1, wmin1)
    candMax0 = __reduce_min_sync(0xffffffffu, candMax0);
    candMin0 = __reduce_min_sync(0xffffffffu, candMin0);
    candMax1 = __reduce_min_sync(0xffffffffu, candMax1);
    candMin1 = __reduce_min_sync(0xffffffffu, candMin1);

    if (lane == 0) {
        const int cell0 = cy * 16 + half * 8 + 2 * w;
        g_cmax[img * NCELLS + cell0] =
            ((unsigned long long)__float_as_uint(wmax0) << 32) | (unsigned)(~candMax0);
        g_cmin[img * NCELLS + cell0] =
            ((unsigned long long)__float_as_uint(wmin0) << 32) | candMin0;
        g_cmax[img * NCELLS + cell0 + 1] =
            ((unsigned long long)__float_as_uint(wmax1) << 32) | (unsigned)(~candMax1);
        g_cmin[img * NCELLS + cell0 + 1] =
            ((unsigned long long)__float_as_uint(wmin1) << 32) | candMin1;
        __threadfence();                     // release: only storing lanes pay the fence
    }

    // ---------------- handoff: last of 32 blocks per image finalizes ----------------
    __syncthreads();
    __shared__ int sLast;
    if (tid == 0) {
        unsigned prev = atomicAdd(&g_cnt[img], 1u);
        int last = (prev == BLOCKS_PER_IMG - 1);
        if (last) g_cnt[img] = 0;            // self-reset for next graph replay
        sLast = last;
    }
    __syncthreads();
    if (!sLast) return;
    __threadfence();                         // acquire side

    // ---------------- Phase 2: finalize (one 128-thread block per image) ----------------
    const int t = img / C_DIM;
    const float sx = (float)ori[t * 2 + 1] / (float)W_DIM;
    const float sy = (float)ori[t * 2 + 0] / (float)H_DIM;

    __shared__ unsigned long long key[NCELLS];
    __shared__ unsigned long long sG[8];     // [0:4) img-max partials, [4:8) img-min partials

    // Each thread owns cells tid and tid+128.
    unsigned long long pM0 = __ldcg(&g_cmax[img * NCELLS + tid]);
    unsigned long long pM1 = __ldcg(&g_cmax[img * NCELLS + tid + 128]);
    unsigned long long pN0 = __ldcg(&g_cmin[img * NCELLS + tid]);
    unsigned long long pN1 = __ldcg(&g_cmin[img * NCELLS + tid + 128]);

    bool valid0 = __uint_as_float((unsigned)(pM0 >> 32)) > THRESH;
    bool valid1 = __uint_as_float((unsigned)(pM1 >> 32)) > THRESH;

    // Unique sort keys: descending score, ascending cell id; invalid cells last (stable by cid).
    unsigned long long k0 = valid0 ? ((pM0 & 0xFFFFFFFF00000000ULL) | (unsigned)(255 - tid))
                                   : (unsigned long long)(unsigned)(255 - tid);
    unsigned long long k1 = valid1 ? ((pM1 & 0xFFFFFFFF00000000ULL) | (unsigned)(255 - (tid + 128)))
                                   : (unsigned long long)(unsigned)(255 - (tid + 128));
    key[tid]       = k0;
    key[tid + 128] = k1;

    // Image-global extrema.
    unsigned long long gm = umaxll(pM0, pM1), gn = uminll(pN0, pN1);
    #pragma unroll
    for (int off = 16; off; off >>= 1) {
        gm = umaxll(gm, __shfl_xor_sync(0xffffffffu, gm, off));
        gn = uminll(gn, __shfl_xor_sync(0xffffffffu, gn, off));
    }
    if (lane == 0) { sG[w] = gm; sG[4 + w] = gn; }

    int nvalid = __syncthreads_count((int)valid0) + __syncthreads_count((int)valid1);

    int rank0 = 0, rank1 = 0;
    #pragma unroll 8
    for (int j = 0; j < NCELLS; j++) {
        unsigned long long kj = key[j];
        rank0 += (kj > k0) ? 1 : 0;
        rank1 += (kj > k1) ? 1 : 0;
    }

    bool any_fg  = (nvalid > 0);
    int fg_count = any_fg ? (nvalid < NUM_FG ? nvalid : NUM_FG) : 1;

    float* o = out + (size_t)img * MAX_PTS * 4;
    #pragma unroll
    for (int i = tid; i < MAX_PTS * 4; i += 128) o[i] = 0.0f;
    __syncthreads();

    if (any_fg) {
        if (rank0 < NUM_FG && valid0) {
            unsigned bits = (unsigned)(pM0 >> 32);
            unsigned pidx = ~(unsigned)(pM0 & 0xffffffffull);
            float* r = o + rank0 * 4;
            r[0] = (float)(pidx % W_DIM) * sx;
            r[1] = (float)(pidx / W_DIM) * sy;
            r[2] = __uint_as_float(bits);
            r[3] = 1.0f;
        }
        if (rank1 < NUM_FG && valid1) {
            unsigned bits = (unsigned)(pM1 >> 32);
            unsigned pidx = ~(unsigned)(pM1 & 0xffffffffull);
            float* r = o + rank1 * 4;
            r[0] = (float)(pidx % W_DIM) * sx;
            r[1] = (float)(pidx / W_DIM) * sy;
            r[2] = __uint_as_float(bits);
            r[3] = 1.0f;
        }
    } else if (tid == 0) {
        unsigned long long m = sG[0];
        #pragma unroll
        for (int i = 1; i < 4; i++) m = umaxll(m, sG[i]);
        unsigned gb = (unsigned)(m >> 32);
        unsigned gi = ~(unsigned)(m & 0xffffffffull);
        o[0] = (float)(gi % W_DIM) * sx;
        o[1] = (float)(gi / W_DIM) * sy;
        o[2] = __uint_as_float(gb);
        o[3] = 1.0f;
    }

    if (tid == 0) {
        unsigned long long n = sG[4];
        #pragma unroll
        for (int i = 1; i < 4; i++) n = uminll(n, sG[4 + i]);
        unsigned bb = (unsigned)(n >> 32);
        unsigned bi = (unsigned)(n & 0xffffffffull);
        float* r = o + fg_count * 4;
        r[0] = (float)(bi % W_DIM) * sx;
        r[1] = (float)(bi / W_DIM) * sy;
        r[2] = __uint_as_float(bb);
        r[3] = 0.0f;
        if (write_nums) {
            float* nums = out + (size_t)NIMG * MAX_PTS * 4;
            nums[img] = (float)(fg_count + NUM_BG);
        }
    }
}

extern "C" void kernel_launch(void* const* d_in, const int* in_sizes, int n_in,
                              void* d_out, int out_size) {
    const float* sim = (const float*)d_in[0];
    // d_in[1] = category_ids (unused by the reference output)
    const int* ori = (const int*)d_in[2];

    int write_nums = (out_size >= NIMG * MAX_PTS * 4 + NIMG) ? 1 : 0;
    fused_kernel<<<NIMG * BLOCKS_PER_IMG, 128>>>(sim, ori, (float*)d_out, write_nums);
}

// round 13
// speedup vs baseline: 1.1572x; 1.1572x over previous
#include <cuda_runtime.h>
#include <stdint.h>

#define T_DIM 8
#define C_DIM 4
#define H_DIM 1024
#define W_DIM 1024
#define NIMG  (T_DIM * C_DIM)
#define NGRID 16
#define NCELLS (NGRID * NGRID)
#define THRESH 0.65f
#define NUM_FG 40
#define NUM_BG 1
#define MAX_PTS 42
#define ROW_F4 (W_DIM / 4)   // 256
#define BLOCKS_PER_IMG 16    // one block per cell-row (16 cells, 2 per warp)

// Scratch (__device__ globals). Each cell has exactly ONE writer warp, and the
// written value is a pure function of the inputs -> plain stores are idempotent
// across graph replays (no init kernel, no atomics needed).
__device__ unsigned long long g_cmax[NIMG * NCELLS]; // (score_bits<<32) | ~flat_idx  (max, min-idx tie-break)
__device__ unsigned long long g_cmin[NIMG * NCELLS]; // (score_bits<<32) |  flat_idx  (min, min-idx tie-break)
__device__ unsigned int       g_cnt[NIMG];           // arrival counters; last block resets to 0

static __device__ __forceinline__ unsigned long long umaxll(unsigned long long a, unsigned long long b){ return a > b ? a : b; }
static __device__ __forceinline__ unsigned long long uminll(unsigned long long a, unsigned long long b){ return a < b ? a : b; }

__global__ void __launch_bounds__(256)
fused_kernel(const float* __restrict__ sim,
             const int*   __restrict__ ori,
             float*       __restrict__ out,
             int write_nums)
{
    const int blk  = blockIdx.x;             // 0..511
    const int img  = blk >> 4;               // 32 images
    const int cy   = blk & 15;               // this block owns cell-row cy (16 cells)
    const int tid  = threadIdx.x;
    const int w    = tid >> 5;               // warp 0..7: owns cells cx = w and w+8
    const int lane = tid & 31;
    const float4* base = (const float4*)(sim + (size_t)img * (H_DIM * W_DIM));

    // Lane geometry inside a chunk (8 rows x 64 cols of one cell):
    //   it in 0..3 covers row pair (it*2 + rsub); lanes 0-15 / 16-31 each cover
    //   a full 256B row -> every LDG.128 is perfectly coalesced.
    const int rsub = lane >> 4;              // 0..1
    const int csub = lane & 15;              // 0..15

    // q = 0..15 linear chunk id: cell cx = w + 8*(q>>3), chunk c = q&7.
    // DRAM-page-friendly mapping: while all warps run q<8 they jointly cover
    // columns 0..511 (contiguous 2KB of every touched row); q>=8 covers 512..1023.
    #define A0(q) ((cy * 64 + ((q) & 7) * 8 + rsub) * ROW_F4 + (w + 8 * ((q) >> 3)) * 16 + csub)

    // Depth-2 software pipeline: 3-buffer ring, loads issued 2 chunks ahead.
    float4 buf[3][4];
    {
        const int a0 = A0(0), a1 = A0(1);
        #pragma unroll
        for (int it = 0; it < 4; it++) buf[0][it] = __ldcs(base + a0 + it * (2 * ROW_F4));
        #pragma unroll
        for (int it = 0; it < 4; it++) buf[1][it] = __ldcs(base + a1 + it * (2 * ROW_F4));
    }

    #pragma unroll
    for (int cc = 0; cc < 2; cc++) {         // two cells per warp: cx = w, then w+8
        float vmax = 0.0f;                   // scores are in [0,1): 0.0f is a safe floor
        float vmin = __uint_as_float(0x7f800000u);  // +inf: safe ceiling, bit-monotone
        int bqmax = cc * 8, bqmin = cc * 8;

        #pragma unroll
        for (int c = 0; c < 8; c++) {
            const int q = cc * 8 + c;
            if (q < 14) {                    // prefetch 2 chunks ahead (crosses cell boundary)
                const int a = A0(q + 2);
                #pragma unroll
                for (int it = 0; it < 4; it++)
                    buf[(q + 2) % 3][it] = __ldcs(base + a + it * (2 * ROW_F4));
            }
            const float4* cur = buf[q % 3];
            // 16-value max/min trees over the current chunk
            float mx0 = fmaxf(fmaxf(cur[0].x, cur[0].y), fmaxf(cur[0].z, cur[0].w));
            float mx1 = fmaxf(fmaxf(cur[1].x, cur[1].y), fmaxf(cur[1].z, cur[1].w));
            float mx2 = fmaxf(fmaxf(cur[2].x, cur[2].y), fmaxf(cur[2].z, cur[2].w));
            float mx3 = fmaxf(fmaxf(cur[3].x, cur[3].y), fmaxf(cur[3].z, cur[3].w));
            float cmax = fmaxf(fmaxf(mx0, mx1), fmaxf(mx2, mx3));
            float mn0 = fminf(fminf(cur[0].x, cur[0].y), fminf(cur[0].z, cur[0].w));
            float mn1 = fminf(fminf(cur[1].x, cur[1].y), fminf(cur[1].z, cur[1].w));
            float mn2 = fminf(fminf(cur[2].x, cur[2].y), fminf(cur[2].z, cur[2].w));
            float mn3 = fminf(fminf(cur[3].x, cur[3].y), fminf(cur[3].z, cur[3].w));
            float cmin = fminf(fminf(mn0, mn1), fminf(mn2, mn3));
            // Chunk-granular deferred tracking. Strict compare keeps the FIRST
            // chunk achieving the extremum (chunks ascend in flat index).
            if (cmax > vmax) { vmax = cmax; bqmax = q; }
            if (cmin < vmin) { vmin = cmin; bqmin = q; }
        }

        // Warp value reductions via single-instruction REDUX (scores positive ->
        // unsigned bit order == float order).
        float wmax = __uint_as_float(__reduce_max_sync(0xffffffffu, __float_as_uint(vmax)));
        float wmin = __uint_as_float(__reduce_min_sync(0xffffffffu, __float_as_uint(vmin)));

        // Deferred index resolution: matching lanes re-load their best chunk
        // (64B each, L2-resident) and scan 16 values DESCENDING so overwrite
        // keeps the smallest flat index (reference first-occurrence semantics).
        unsigned candMax = 0xffffffffu, candMin = 0xffffffffu;
        if (vmax == wmax) {
            const int q = bqmax;
            const int a = A0(q);
            const int row0 = cy * 64 + (q & 7) * 8 + rsub;
            const int col  = ((w + 8 * (q >> 3)) * 16 + csub) * 4;
            #pragma unroll
            for (int it = 3; it >= 0; it--) {
                float4 v = __ldcg(base + a + it * (2 * ROW_F4));
                unsigned i0 = (unsigned)((row0 + it * 2) * W_DIM + col);
                if (v.w == wmax) candMax = i0 + 3;
                if (v.z == wmax) candMax = i0 + 2;
                if (v.y == wmax) candMax = i0 + 1;
                if (v.x == wmax) candMax = i0;
            }
        }
        if (vmin == wmin) {
            const int q = bqmin;
            const int a = A0(q);
            const int row0 = cy * 64 + (q & 7) * 8 + rsub;
            const int col  = ((w + 8 * (q >> 3)) * 16 + csub) * 4;
            #pragma unroll
            for (int it = 3; it >= 0; it--) {
                float4 v = __ldcg(base + a + it * (2 * ROW_F4));
                unsigned i0 = (unsigned)((row0 + it * 2) * W_DIM + col);
                if (v.w == wmin) candMin = i0 + 3;
                if (v.z == wmin) candMin = i0 + 2;
                if (v.y == wmin) candMin = i0 + 1;
                if (v.x == wmin) candMin = i0;
            }
        }
        candMax = __reduce_min_sync(0xffffffffu, candMax);
        candMin = __reduce_min_sync(0xffffffffu, candMin);

        if (lane == 0) {
            const int cell = cy * 16 + w + 8 * cc;
            g_cmax[img * NCELLS + cell] =
                ((unsigned long long)__float_as_uint(wmax) << 32) | (unsigned)(~candMax);
            g_cmin[img * NCELLS + cell] =
                ((unsigned long long)__float_as_uint(wmin) << 32) | candMin;
        }
    }

    // ---------------- handoff: last of 16 blocks per image finalizes ----------------
    if (lane == 0) __threadfence();         // only the storing lanes need the release fence
    __syncthreads();
    __shared__ int sLast;
    if (tid == 0) {
        unsigned prev = atomicAdd(&g_cnt[img], 1u);
        int last = (prev == BLOCKS_PER_IMG - 1);
        if (last) g_cnt[img] = 0;           // self-reset for next graph replay
        sLast = last;
    }
    __syncthreads();
    if (!sLast) return;
    __threadfence();                        // acquire side

    // ---------------- Phase 2: finalize (one block per image) ----------------
    const int t = img / C_DIM;
    const float sx = (float)ori[t * 2 + 1] / (float)W_DIM;
    const float sy = (float)ori[t * 2 + 0] / (float)H_DIM;

    __shared__ unsigned long long key[NCELLS];
    __shared__ unsigned long long sG[16];   // [0:8) img-max partials, [8:16) img-min partials

    unsigned long long pM = __ldcg(&g_cmax[img * NCELLS + tid]);
    unsigned long long pN = __ldcg(&g_cmin[img * NCELLS + tid]);
    unsigned bits = (unsigned)(pM >> 32);
    unsigned pidx = ~(unsigned)(pM & 0xffffffffull);
    bool valid = __uint_as_float(bits) > THRESH;   // fg cell iff its max exceeds threshold

    // Unique sort key: descending score, ascending cell id; invalid cells last (stable by cid).
    unsigned long long k = valid ? ((pM & 0xFFFFFFFF00000000ULL) | (unsigned)(255 - tid))
                                 : (unsigned long long)(unsigned)(255 - tid);
    key[tid] = k;

    // Image-global extrema.
    unsigned long long gm = pM, gn = pN;
    #pragma unroll
    for (int off = 16; off; off >>= 1) {
        gm = umaxll(gm, __shfl_xor_sync(0xffffffffu, gm, off));
        gn = uminll(gn, __shfl_xor_sync(0xffffffffu, gn, off));
    }
    if (lane == 0) { sG[w] = gm; sG[8 + w] = gn; }

    int nvalid = __syncthreads_count((int)valid);

    int rank = 0;
    #pragma unroll 8
    for (int j = 0; j < NCELLS; j++) rank += (key[j] > k) ? 1 : 0;

    bool any_fg  = (nvalid > 0);
    int fg_count = any_fg ? (nvalid < NUM_FG ? nvalid : NUM_FG) : 1;

    float* o = out + (size_t)img * MAX_PTS * 4;
    if (tid < MAX_PTS * 4) o[tid] = 0.0f;   // 168 < 256: full zero of this image's block
    __syncthreads();

    if (any_fg) {
        if (rank < NUM_FG && valid) {
            float s  = __uint_as_float(bits);
            float px = (float)(pidx % W_DIM);
            float py = (float)(pidx / W_DIM);
            float* r = o + rank * 4;
            r[0] = px * sx; r[1] = py * sy; r[2] = s; r[3] = 1.0f;
        }
    } else if (tid == 0) {
        unsigned long long m = sG[0];
        #pragma unroll
        for (int i = 1; i < 8; i++) m = umaxll(m, sG[i]);
        unsigned gb = (unsigned)(m >> 32);
        unsigned gi = ~(unsigned)(m & 0xffffffffull);
        o[0] = (float)(gi % W_DIM) * sx;
        o[1] = (float)(gi / W_DIM) * sy;
        o[2] = __uint_as_float(gb);
        o[3] = 1.0f;
    }

    if (tid == 0) {
        unsigned long long n = sG[8];
        #pragma unroll
        for (int i = 1; i < 8; i++) n = uminll(n, sG[8 + i]);
        unsigned bb = (unsigned)(n >> 32);
        unsigned bi = (unsigned)(n & 0xffffffffull);
        float* r = o + fg_count * 4;
        r[0] = (float)(bi % W_DIM) * sx;
        r[1] = (float)(bi / W_DIM) * sy;
        r[2] = __uint_as_float(bb);
        r[3] = 0.0f;
        if (write_nums) {
            float* nums = out + (size_t)NIMG * MAX_PTS * 4;
            nums[img] = (float)(fg_count + NUM_BG);
        }
    }
}

extern "C" void kernel_launch(void* const* d_in, const int* in_sizes, int n_in,
                              void* d_out, int out_size) {
    const float* sim = (const float*)d_in[0];
    // d_in[1] = category_ids (unused by the reference output)
    const int* ori = (const int*)d_in[2];

    int write_nums = (out_size >= NIMG * MAX_PTS * 4 + NIMG) ? 1 : 0;
    fused_kernel<<<NIMG * BLOCKS_PER_IMG, 256>>>(sim, ori, (float*)d_out, write_nums);
}